// round 3
// baseline (speedup 1.0000x reference)
#include <cuda_runtime.h>
#include <math.h>

// Problem constants
#define T_TOTAL 8192     // m*n = 8*1024 tokens
#define N_PER_B 1024
#define NCTX    512
#define DMODEL  256
#define HEADS   8
#define DHEAD   32
#define LAYERS  6
#define FFDIM   1024

// Scratch (device globals — no allocation allowed)
__device__ float g_zin[T_TOTAL * 10];
__device__ float g_ln [T_TOTAL * DMODEL];
__device__ float g_qkv[T_TOTAL * 3 * DMODEL];
__device__ float g_att[T_TOTAL * DMODEL];
__device__ float g_ff [T_TOTAL * FFDIM];
__device__ float g_z  [T_TOTAL * DMODEL];

// ---------------------------------------------------------------------------
// Build encoder input features: [x(8), y(1), flag(1)] per token
// ---------------------------------------------------------------------------
__global__ void build_zin_kernel(const float* __restrict__ xc,
                                 const float* __restrict__ yc,
                                 const float* __restrict__ xt,
                                 float* __restrict__ zin) {
    int t = blockIdx.x * blockDim.x + threadIdx.x;
    if (t >= T_TOTAL) return;
    int b = t >> 10;
    int i = t & 1023;
    float* o = zin + (size_t)t * 10;
    if (i < NCTX) {
        const float* xp = xc + ((size_t)b * NCTX + i) * 8;
        #pragma unroll
        for (int j = 0; j < 8; j++) o[j] = xp[j];
        o[8] = yc[(size_t)b * NCTX + i];
        o[9] = 0.0f;
    } else {
        const float* xp = xt + ((size_t)b * NCTX + (i - NCTX)) * 8;
        #pragma unroll
        for (int j = 0; j < 8; j++) o[j] = xp[j];
        o[8] = 0.0f;
        o[9] = 1.0f;
    }
}

// ---------------------------------------------------------------------------
// Tiled SGEMM: C[T_TOTAL x N] = op(A[T_TOTAL x K] @ B[K x N] + bias)
// BM=128, BN=64, BK=16, 256 threads, 8x4 microtile.
// RELU: apply relu. ACC: C += result (residual add).
// ---------------------------------------------------------------------------
template<int RELU, int ACC>
__global__ __launch_bounds__(256) void sgemm_kernel(
    const float* __restrict__ A, const float* __restrict__ B,
    const float* __restrict__ bias, float* __restrict__ C,
    int N, int K)
{
    const int BM = 128, BN = 64, BK = 16;
    __shared__ float As[BK][BM + 1];   // padded: conflict-free stores/reads
    __shared__ float Bs[BK][BN];
    int bm = blockIdx.y * BM;
    int bn = blockIdx.x * BN;
    int tid = threadIdx.x;
    int tx = tid & 15;        // n-dim, 4 cols each
    int ty = tid >> 4;        // m-dim, 8 rows each

    float acc[8][4];
    #pragma unroll
    for (int i = 0; i < 8; i++)
        #pragma unroll
        for (int j = 0; j < 4; j++) acc[i][j] = 0.0f;

    for (int k0 = 0; k0 < K; k0 += BK) {
        #pragma unroll
        for (int i = 0; i < 8; i++) {           // 2048 A elems
            int idx = tid + i * 256;
            int m = idx >> 4, k = idx & 15;
            As[k][m] = (k0 + k < K) ? A[(size_t)(bm + m) * K + k0 + k] : 0.0f;
        }
        #pragma unroll
        for (int i = 0; i < 4; i++) {           // 1024 B elems
            int idx = tid + i * 256;
            int k = idx >> 6, n = idx & 63;
            Bs[k][n] = (k0 + k < K) ? B[(size_t)(k0 + k) * N + bn + n] : 0.0f;
        }
        __syncthreads();
        #pragma unroll
        for (int k = 0; k < BK; k++) {
            float a[8];
            #pragma unroll
            for (int i = 0; i < 8; i++) a[i] = As[k][ty * 8 + i];
            float4 b4 = *(const float4*)&Bs[k][tx * 4];
            float b[4] = {b4.x, b4.y, b4.z, b4.w};
            #pragma unroll
            for (int i = 0; i < 8; i++)
                #pragma unroll
                for (int j = 0; j < 4; j++)
                    acc[i][j] += a[i] * b[j];
        }
        __syncthreads();
    }

    #pragma unroll
    for (int i = 0; i < 8; i++) {
        int row = bm + ty * 8 + i;
        #pragma unroll
        for (int j = 0; j < 4; j++) {
            int col = bn + tx * 4 + j;
            float v = acc[i][j] + bias[col];
            if (RELU) v = fmaxf(v, 0.0f);
            size_t idx = (size_t)row * N + col;
            if (ACC) C[idx] += v; else C[idx] = v;
        }
    }
}

// ---------------------------------------------------------------------------
// LayerNorm: warp per token, 8 warps/block
// ---------------------------------------------------------------------------
__global__ __launch_bounds__(256) void ln_kernel(
    const float* __restrict__ z, const float* __restrict__ gamma,
    const float* __restrict__ beta, float* __restrict__ out)
{
    int warp = threadIdx.x >> 5;
    int lane = threadIdx.x & 31;
    int t = blockIdx.x * 8 + warp;
    const float* zp = z + (size_t)t * DMODEL;

    float4 a = *(const float4*)(zp + lane * 4);
    float4 b = *(const float4*)(zp + 128 + lane * 4);
    float s  = a.x + a.y + a.z + a.w + b.x + b.y + b.z + b.w;
    float sq = a.x*a.x + a.y*a.y + a.z*a.z + a.w*a.w
             + b.x*b.x + b.y*b.y + b.z*b.z + b.w*b.w;
    #pragma unroll
    for (int o = 16; o > 0; o >>= 1) {
        s  += __shfl_xor_sync(0xffffffffu, s,  o);
        sq += __shfl_xor_sync(0xffffffffu, sq, o);
    }
    float mu = s * (1.0f / DMODEL);
    float var = sq * (1.0f / DMODEL) - mu * mu;
    float rs = rsqrtf(var + 1e-5f);

    float* op = out + (size_t)t * DMODEL;
    float4 g0 = *(const float4*)(gamma + lane * 4);
    float4 g1 = *(const float4*)(gamma + 128 + lane * 4);
    float4 be0 = *(const float4*)(beta + lane * 4);
    float4 be1 = *(const float4*)(beta + 128 + lane * 4);
    float4 o0, o1;
    o0.x = (a.x - mu) * rs * g0.x + be0.x;
    o0.y = (a.y - mu) * rs * g0.y + be0.y;
    o0.z = (a.z - mu) * rs * g0.z + be0.z;
    o0.w = (a.w - mu) * rs * g0.w + be0.w;
    o1.x = (b.x - mu) * rs * g1.x + be1.x;
    o1.y = (b.y - mu) * rs * g1.y + be1.y;
    o1.z = (b.z - mu) * rs * g1.z + be1.z;
    o1.w = (b.w - mu) * rs * g1.w + be1.w;
    *(float4*)(op + lane * 4) = o0;
    *(float4*)(op + 128 + lane * 4) = o1;
}

// ---------------------------------------------------------------------------
// Fused masked attention (TNP-D): every row attends to the 512 context keys;
// target rows (>=512) additionally attend to themselves. Online softmax,
// K/V staged in shared in 128-key chunks. Block = (qchunk, head, batch),
// thread = one query row.
// ---------------------------------------------------------------------------
__global__ __launch_bounds__(256) void attn_kernel(
    const float* __restrict__ qkv, float* __restrict__ out)
{
    int b = blockIdx.z, h = blockIdx.y;
    int qrow = blockIdx.x * 256 + threadIdx.x;
    int token = b * N_PER_B + qrow;
    const float scale = 0.17677669529663689f;  // 1/sqrt(32)

    float q[DHEAD];
    const float* qp = qkv + (size_t)token * 768 + h * DHEAD;
    #pragma unroll
    for (int d = 0; d < DHEAD; d++) q[d] = qp[d] * scale;

    float mval = -1e30f, l = 0.0f;
    float acc[DHEAD];
    #pragma unroll
    for (int d = 0; d < DHEAD; d++) acc[d] = 0.0f;

    __shared__ float sK[128 * DHEAD];
    __shared__ float sV[128 * DHEAD];

    for (int c = 0; c < 4; c++) {               // 4 chunks of 128 context keys
        __syncthreads();
        for (int i = threadIdx.x; i < 128 * DHEAD; i += 256) {
            int kk = i >> 5, d = i & 31;
            size_t kt = (size_t)(b * N_PER_B + c * 128 + kk) * 768;
            sK[i] = qkv[kt + 256 + h * DHEAD + d];
            sV[i] = qkv[kt + 512 + h * DHEAD + d];
        }
        __syncthreads();
        for (int j = 0; j < 128; j++) {
            const float* kp = sK + j * DHEAD;
            const float* vp = sV + j * DHEAD;
            float s = 0.0f;
            #pragma unroll
            for (int d = 0; d < DHEAD; d++) s += q[d] * kp[d];
            float nm = fmaxf(mval, s);
            float corr = __expf(mval - nm);
            float p = __expf(s - nm);
            l = l * corr + p;
            #pragma unroll
            for (int d = 0; d < DHEAD; d++) acc[d] = acc[d] * corr + p * vp[d];
            mval = nm;
        }
    }

    if (qrow >= NCTX) {                          // target self-attention term
        const float* kp = qkv + (size_t)token * 768 + 256 + h * DHEAD;
        const float* vp = kp + 256;
        float s = 0.0f;
        #pragma unroll
        for (int d = 0; d < DHEAD; d++) s += q[d] * kp[d];
        float nm = fmaxf(mval, s);
        float corr = __expf(mval - nm);
        float p = __expf(s - nm);
        l = l * corr + p;
        #pragma unroll
        for (int d = 0; d < DHEAD; d++) acc[d] = acc[d] * corr + p * vp[d];
        mval = nm;
    }

    float inv = 1.0f / l;
    float* op = out + (size_t)token * DMODEL + h * DHEAD;
    #pragma unroll
    for (int d = 0; d < DHEAD; d++) op[d] = acc[d] * inv;
}

// ---------------------------------------------------------------------------
// Final copy z -> d_out
// ---------------------------------------------------------------------------
__global__ void copy_kernel(const float* __restrict__ src, float* __restrict__ dst) {
    int i = blockIdx.x * blockDim.x + threadIdx.x;
    ((float4*)dst)[i] = ((const float4*)src)[i];
}

// ---------------------------------------------------------------------------
// Launch
// ---------------------------------------------------------------------------
extern "C" void kernel_launch(void* const* d_in, const int* in_sizes, int n_in,
                              void* d_out, int out_size) {
    const float* xc     = (const float*)d_in[0];
    const float* yc     = (const float*)d_in[1];
    const float* xt     = (const float*)d_in[2];
    const float* enc_W1 = (const float*)d_in[3];
    const float* enc_b1 = (const float*)d_in[4];
    const float* enc_W2 = (const float*)d_in[5];
    const float* enc_b2 = (const float*)d_in[6];
    const float* Wqkv   = (const float*)d_in[7];
    const float* bqkv   = (const float*)d_in[8];
    const float* Wo     = (const float*)d_in[9];
    const float* bo     = (const float*)d_in[10];
    const float* ln1_g  = (const float*)d_in[11];
    const float* ln1_b  = (const float*)d_in[12];
    const float* ln2_g  = (const float*)d_in[13];
    const float* ln2_b  = (const float*)d_in[14];
    const float* Wff1   = (const float*)d_in[15];
    const float* bff1   = (const float*)d_in[16];
    const float* Wff2   = (const float*)d_in[17];
    const float* bff2   = (const float*)d_in[18];

    float *zin, *lnb, *qkvb, *attb, *ffb, *zb;
    cudaGetSymbolAddress((void**)&zin,  g_zin);
    cudaGetSymbolAddress((void**)&lnb,  g_ln);
    cudaGetSymbolAddress((void**)&qkvb, g_qkv);
    cudaGetSymbolAddress((void**)&attb, g_att);
    cudaGetSymbolAddress((void**)&ffb,  g_ff);
    cudaGetSymbolAddress((void**)&zb,   g_z);

    // Encoder
    build_zin_kernel<<<32, 256>>>(xc, yc, xt, zin);
    sgemm_kernel<1, 0><<<dim3(DMODEL / 64, T_TOTAL / 128), 256>>>(
        zin, enc_W1, enc_b1, lnb, DMODEL, 10);
    sgemm_kernel<0, 0><<<dim3(DMODEL / 64, T_TOTAL / 128), 256>>>(
        lnb, enc_W2, enc_b2, zb, DMODEL, DMODEL);

    // Transformer layers
    for (int l = 0; l < LAYERS; l++) {
        ln_kernel<<<T_TOTAL / 8, 256>>>(zb, ln1_g + l * DMODEL, ln1_b + l * DMODEL, lnb);
        sgemm_kernel<0, 0><<<dim3(768 / 64, T_TOTAL / 128), 256>>>(
            lnb, Wqkv + (size_t)l * DMODEL * 768, bqkv + l * 768, qkvb, 768, DMODEL);
        attn_kernel<<<dim3(4, HEADS, 8), 256>>>(qkvb, attb);
        sgemm_kernel<0, 1><<<dim3(DMODEL / 64, T_TOTAL / 128), 256>>>(
            attb, Wo + (size_t)l * DMODEL * DMODEL, bo + l * DMODEL, zb, DMODEL, DMODEL);
        ln_kernel<<<T_TOTAL / 8, 256>>>(zb, ln2_g + l * DMODEL, ln2_b + l * DMODEL, lnb);
        sgemm_kernel<1, 0><<<dim3(FFDIM / 64, T_TOTAL / 128), 256>>>(
            lnb, Wff1 + (size_t)l * DMODEL * FFDIM, bff1 + l * FFDIM, ffb, FFDIM, DMODEL);
        sgemm_kernel<0, 1><<<dim3(DMODEL / 64, T_TOTAL / 128), 256>>>(
            ffb, Wff2 + (size_t)l * FFDIM * DMODEL, bff2 + l * DMODEL, zb, DMODEL, FFDIM);
    }

    copy_kernel<<<(T_TOTAL * DMODEL / 4) / 256, 256>>>(zb, (float*)d_out);
}

// round 5
// speedup vs baseline: 1.6258x; 1.6258x over previous
#include <cuda_runtime.h>
#include <cuda_bf16.h>
#include <math.h>
#include <stdint.h>

#define T_TOTAL 8192
#define N_PER_B 1024
#define NCTX    512
#define DMODEL  256
#define HEADS   8
#define DHEAD   32
#define LAYERS  6
#define FFDIM   1024

typedef __nv_bfloat16 bf16;

// ---------------------------------------------------------------------------
// Scratch (device globals — no allocation allowed)
// ---------------------------------------------------------------------------
__device__ float g_zin[T_TOTAL * 10];
__device__ float g_qkv[T_TOTAL * 768];
__device__ float g_z  [T_TOTAL * DMODEL];
__device__ bf16  g_ahi[T_TOTAL * DMODEL];
__device__ bf16  g_alo[T_TOTAL * DMODEL];
__device__ bf16  g_fhi[T_TOTAL * FFDIM];
__device__ bf16  g_flo[T_TOTAL * FFDIM];
#define WT_TOTAL 4784128
__device__ bf16  g_wThi[WT_TOTAL];
__device__ bf16  g_wTlo[WT_TOTAL];

// ---------------------------------------------------------------------------
// PTX helpers (base-target features only: cp.async / ldmatrix / mma.sync)
// ---------------------------------------------------------------------------
__device__ __forceinline__ uint32_t smem_u32(const void* p) {
    uint32_t a;
    asm("{ .reg .u64 t; cvta.to.shared.u64 t, %1; cvt.u32.u64 %0, t; }"
        : "=r"(a) : "l"(p));
    return a;
}

__device__ __forceinline__ void cp16(uint32_t saddr, const void* g) {
    asm volatile("cp.async.cg.shared.global [%0], [%1], 16;"
                 :: "r"(saddr), "l"(g) : "memory");
}
__device__ __forceinline__ void cp_commit() {
    asm volatile("cp.async.commit_group;" ::: "memory");
}
__device__ __forceinline__ void cp_wait1() {
    asm volatile("cp.async.wait_group 1;" ::: "memory");
}
__device__ __forceinline__ void cp_wait0() {
    asm volatile("cp.async.wait_group 0;" ::: "memory");
}

__device__ __forceinline__ void ldm4(uint32_t* d, uint32_t addr) {
    asm volatile("ldmatrix.sync.aligned.m8n8.x4.shared.b16 {%0,%1,%2,%3}, [%4];"
        : "=r"(d[0]), "=r"(d[1]), "=r"(d[2]), "=r"(d[3]) : "r"(addr));
}

__device__ __forceinline__ void mma16816(float* c, const uint32_t* a,
                                         uint32_t b0, uint32_t b1) {
    asm volatile(
        "mma.sync.aligned.m16n8k16.row.col.f32.bf16.bf16.f32 "
        "{%0,%1,%2,%3}, {%4,%5,%6,%7}, {%8,%9}, {%0,%1,%2,%3};"
        : "+f"(c[0]), "+f"(c[1]), "+f"(c[2]), "+f"(c[3])
        : "r"(a[0]), "r"(a[1]), "r"(a[2]), "r"(a[3]), "r"(b0), "r"(b1));
}

// ---------------------------------------------------------------------------
// bf16 hi/lo split helpers
// ---------------------------------------------------------------------------
__device__ __forceinline__ unsigned pk(bf16 a, bf16 b) {
    unsigned short ua = *(unsigned short*)&a;
    unsigned short ub = *(unsigned short*)&b;
    return (unsigned)ua | ((unsigned)ub << 16);
}

__device__ __forceinline__ void store_bf16pair4(bf16* ph, bf16* pl, float4 v) {
    bf16 h0 = __float2bfloat16(v.x), h1 = __float2bfloat16(v.y);
    bf16 h2 = __float2bfloat16(v.z), h3 = __float2bfloat16(v.w);
    bf16 l0 = __float2bfloat16(v.x - __bfloat162float(h0));
    bf16 l1 = __float2bfloat16(v.y - __bfloat162float(h1));
    bf16 l2 = __float2bfloat16(v.z - __bfloat162float(h2));
    bf16 l3 = __float2bfloat16(v.w - __bfloat162float(h3));
    uint2 uh; uh.x = pk(h0, h1); uh.y = pk(h2, h3);
    uint2 ul; ul.x = pk(l0, l1); ul.y = pk(l2, l3);
    *(uint2*)ph = uh;
    *(uint2*)pl = ul;
}

__device__ __forceinline__ void store_bf16pair2(bf16* ph, bf16* pl, float a, float b) {
    bf16 h0 = __float2bfloat16(a), h1 = __float2bfloat16(b);
    bf16 l0 = __float2bfloat16(a - __bfloat162float(h0));
    bf16 l1 = __float2bfloat16(b - __bfloat162float(h1));
    *(unsigned*)ph = pk(h0, h1);
    *(unsigned*)pl = pk(l0, l1);
}

// ---------------------------------------------------------------------------
// Weight transpose + bf16 split:  W[K,N] fp32 -> WT[N,K] bf16 hi/lo
// ---------------------------------------------------------------------------
__global__ void transpose_split(const float* __restrict__ W,
                                bf16* __restrict__ oh, bf16* __restrict__ ol,
                                int K, int N) {
    __shared__ float t[32][33];
    int n0 = blockIdx.x * 32, k0 = blockIdx.y * 32;
    int tx = threadIdx.x, ty = threadIdx.y;
    #pragma unroll
    for (int i = 0; i < 4; i++)
        t[ty + i * 8][tx] = W[(size_t)(k0 + ty + i * 8) * N + n0 + tx];
    __syncthreads();
    #pragma unroll
    for (int i = 0; i < 4; i++) {
        float v = t[tx][ty + i * 8];
        bf16 h = __float2bfloat16(v);
        bf16 l = __float2bfloat16(v - __bfloat162float(h));
        size_t o = (size_t)(n0 + ty + i * 8) * K + k0 + tx;
        oh[o] = h; ol[o] = l;
    }
}

// ---------------------------------------------------------------------------
// Warp-MMA GEMM: C[8192 x N] = (Ahi+Alo)[8192 x K] @ (Bhi+Blo)[N x K]^T + bias
// 3-pass bf16 split (hi*hi + lo*hi + hi*lo), fp32 register accumulation.
// CTA tile BM x 128, BK=32, 8 warps as 2(m) x 4(n), warp tile (BM/2) x 32.
// Smem rows padded to 80B -> conflict-free ldmatrix. cp.async double-buffered.
// ---------------------------------------------------------------------------
template<int BM, int RELU, int RES, int OUTBF>
__global__ __launch_bounds__(256, 2) void gemm_mma(
    const bf16* __restrict__ Ahi, const bf16* __restrict__ Alo,
    const bf16* __restrict__ Bhi, const bf16* __restrict__ Blo,
    const float* __restrict__ bias,
    float* __restrict__ Cf, bf16* __restrict__ Chi, bf16* __restrict__ Clo,
    int N, int K)
{
    constexpr int MI = BM / 32;                 // m16 frags per warp
    constexpr int STAGE = (2 * BM + 256) * 80;  // bytes per stage
    constexpr int OAh = 0;
    constexpr int OAl = BM * 80;
    constexpr int OBh = 2 * BM * 80;
    constexpr int OBl = 2 * BM * 80 + 128 * 80;

    extern __shared__ char smem[];
    const int tid = threadIdx.x;
    const int wid = tid >> 5, lane = tid & 31;
    const int wm = wid & 1, wn = wid >> 1;
    const int bn = blockIdx.x * 128, bm = blockIdx.y * BM;
    const uint32_t sb = smem_u32(smem);

    float c[MI][4][4];
    #pragma unroll
    for (int i = 0; i < MI; i++)
        #pragma unroll
        for (int j = 0; j < 4; j++)
            #pragma unroll
            for (int q = 0; q < 4; q++) c[i][j][q] = 0.0f;

    // per-lane ldmatrix addressing
    const int r8 = lane & 7, g8 = lane >> 3;
    const int a_row = wm * (BM / 2) + (g8 & 1) * 8 + r8;
    const int a_kof = (g8 >> 1) * 16;           // bytes
    const int b_row = wn * 32 + (g8 >> 1) * 8 + r8;
    const int b_kof = (g8 & 1) * 16;

    auto load_stage = [&](int s, int buf) {
        const int k0 = s * 32;
        const uint32_t sbase = sb + buf * STAGE;
        #pragma unroll
        for (int i = tid; i < BM * 4; i += 256) {
            int r = i >> 2, cc = i & 3;
            size_t g = (size_t)(bm + r) * K + k0 + cc * 8;
            uint32_t so = sbase + r * 80 + cc * 16;
            cp16(so + OAh, Ahi + g);
            cp16(so + OAl, Alo + g);
        }
        #pragma unroll
        for (int i = tid; i < 512; i += 256) {
            int r = i >> 2, cc = i & 3;
            size_t g = (size_t)(bn + r) * K + k0 + cc * 8;
            uint32_t so = sbase + r * 80 + cc * 16;
            cp16(so + OBh, Bhi + g);
            cp16(so + OBl, Blo + g);
        }
        cp_commit();
    };

    const int S = K >> 5;
    load_stage(0, 0);
    for (int s = 0; s < S; s++) {
        if (s + 1 < S) { load_stage(s + 1, (s + 1) & 1); cp_wait1(); }
        else cp_wait0();
        __syncthreads();

        const uint32_t sbase = sb + (s & 1) * STAGE;
        #pragma unroll
        for (int ks = 0; ks < 2; ks++) {
            uint32_t a[MI][4], bh[2][4], bl[2][4];
            #pragma unroll
            for (int mi = 0; mi < MI; mi++)
                ldm4(a[mi], sbase + OAh + (uint32_t)(a_row + mi * 16) * 80 + ks * 32 + a_kof);
            #pragma unroll
            for (int nj = 0; nj < 2; nj++)
                ldm4(bh[nj], sbase + OBh + (uint32_t)(b_row + nj * 16) * 80 + ks * 32 + b_kof);
            // pass 1: Ahi * Bhi
            #pragma unroll
            for (int mi = 0; mi < MI; mi++)
                #pragma unroll
                for (int ni = 0; ni < 4; ni++)
                    mma16816(c[mi][ni], a[mi], bh[ni >> 1][(ni & 1) * 2], bh[ni >> 1][(ni & 1) * 2 + 1]);
            // pass 2: Ahi * Blo
            #pragma unroll
            for (int nj = 0; nj < 2; nj++)
                ldm4(bl[nj], sbase + OBl + (uint32_t)(b_row + nj * 16) * 80 + ks * 32 + b_kof);
            #pragma unroll
            for (int mi = 0; mi < MI; mi++)
                #pragma unroll
                for (int ni = 0; ni < 4; ni++)
                    mma16816(c[mi][ni], a[mi], bl[ni >> 1][(ni & 1) * 2], bl[ni >> 1][(ni & 1) * 2 + 1]);
            // pass 3: Alo * Bhi  (overwrite A frags)
            #pragma unroll
            for (int mi = 0; mi < MI; mi++)
                ldm4(a[mi], sbase + OAl + (uint32_t)(a_row + mi * 16) * 80 + ks * 32 + a_kof);
            #pragma unroll
            for (int mi = 0; mi < MI; mi++)
                #pragma unroll
                for (int ni = 0; ni < 4; ni++)
                    mma16816(c[mi][ni], a[mi], bh[ni >> 1][(ni & 1) * 2], bh[ni >> 1][(ni & 1) * 2 + 1]);
        }
        __syncthreads();
    }

    // Epilogue: direct stores; lanes 0-3 cover 8 consecutive floats (full sector)
    const int quad = lane >> 2, tc = lane & 3;
    #pragma unroll
    for (int mi = 0; mi < MI; mi++) {
        #pragma unroll
        for (int ni = 0; ni < 4; ni++) {
            int row0 = bm + wm * (BM / 2) + mi * 16 + quad;
            int col = bn + wn * 32 + ni * 8 + tc * 2;
            float b0 = bias[col], b1 = bias[col + 1];
            float v00 = c[mi][ni][0] + b0, v01 = c[mi][ni][1] + b1;
            float v10 = c[mi][ni][2] + b0, v11 = c[mi][ni][3] + b1;
            if (RELU) {
                v00 = fmaxf(v00, 0.0f); v01 = fmaxf(v01, 0.0f);
                v10 = fmaxf(v10, 0.0f); v11 = fmaxf(v11, 0.0f);
            }
            size_t o0 = (size_t)row0 * N + col;
            size_t o1 = o0 + (size_t)8 * N;
            if (OUTBF) {
                store_bf16pair2(Chi + o0, Clo + o0, v00, v01);
                store_bf16pair2(Chi + o1, Clo + o1, v10, v11);
            } else if (RES) {
                float2 z0 = *(float2*)(Cf + o0);
                float2 z1 = *(float2*)(Cf + o1);
                z0.x += v00; z0.y += v01; z1.x += v10; z1.y += v11;
                *(float2*)(Cf + o0) = z0;
                *(float2*)(Cf + o1) = z1;
            } else {
                float2 w0 = {v00, v01}, w1 = {v10, v11};
                *(float2*)(Cf + o0) = w0;
                *(float2*)(Cf + o1) = w1;
            }
        }
    }
}

// ---------------------------------------------------------------------------
// Build encoder input features: [x(8), y(1), flag(1)] per token
// ---------------------------------------------------------------------------
__global__ void build_zin_kernel(const float* __restrict__ xc,
                                 const float* __restrict__ yc,
                                 const float* __restrict__ xt,
                                 float* __restrict__ zin) {
    int t = blockIdx.x * blockDim.x + threadIdx.x;
    if (t >= T_TOTAL) return;
    int b = t >> 10;
    int i = t & 1023;
    float* o = zin + (size_t)t * 10;
    if (i < NCTX) {
        const float* xp = xc + ((size_t)b * NCTX + i) * 8;
        #pragma unroll
        for (int j = 0; j < 8; j++) o[j] = xp[j];
        o[8] = yc[(size_t)b * NCTX + i];
        o[9] = 0.0f;
    } else {
        const float* xp = xt + ((size_t)b * NCTX + (i - NCTX)) * 8;
        #pragma unroll
        for (int j = 0; j < 8; j++) o[j] = xp[j];
        o[8] = 0.0f;
        o[9] = 1.0f;
    }
}

// ---------------------------------------------------------------------------
// enc1: fp32 SGEMM (K=10) with relu, outputs bf16 hi/lo pair.
// ---------------------------------------------------------------------------
__global__ __launch_bounds__(256) void enc1_kernel(
    const float* __restrict__ A, const float* __restrict__ B,
    const float* __restrict__ bias, bf16* __restrict__ Chi, bf16* __restrict__ Clo)
{
    const int BM = 128, BN = 64, BK = 16, N = DMODEL, K = 10;
    __shared__ float As[BK][BM + 1];
    __shared__ float Bs[BK][BN];
    int bm = blockIdx.y * BM;
    int bn = blockIdx.x * BN;
    int tid = threadIdx.x;
    int tx = tid & 15;
    int ty = tid >> 4;

    float acc[8][4];
    #pragma unroll
    for (int i = 0; i < 8; i++)
        #pragma unroll
        for (int j = 0; j < 4; j++) acc[i][j] = 0.0f;

    #pragma unroll
    for (int i = 0; i < 8; i++) {
        int idx = tid + i * 256;
        int m = idx >> 4, k = idx & 15;
        As[k][m] = (k < K) ? A[(size_t)(bm + m) * K + k] : 0.0f;
    }
    #pragma unroll
    for (int i = 0; i < 4; i++) {
        int idx = tid + i * 256;
        int k = idx >> 6, n = idx & 63;
        Bs[k][n] = (k < K) ? B[(size_t)k * N + bn + n] : 0.0f;
    }
    __syncthreads();
    #pragma unroll
    for (int k = 0; k < BK; k++) {
        float a[8];
        #pragma unroll
        for (int i = 0; i < 8; i++) a[i] = As[k][ty * 8 + i];
        float4 b4 = *(const float4*)&Bs[k][tx * 4];
        float b[4] = {b4.x, b4.y, b4.z, b4.w};
        #pragma unroll
        for (int i = 0; i < 8; i++)
            #pragma unroll
            for (int j = 0; j < 4; j++)
                acc[i][j] += a[i] * b[j];
    }

    #pragma unroll
    for (int i = 0; i < 8; i++) {
        int row = bm + ty * 8 + i;
        float4 v;
        v.x = fmaxf(acc[i][0] + bias[bn + tx * 4 + 0], 0.0f);
        v.y = fmaxf(acc[i][1] + bias[bn + tx * 4 + 1], 0.0f);
        v.z = fmaxf(acc[i][2] + bias[bn + tx * 4 + 2], 0.0f);
        v.w = fmaxf(acc[i][3] + bias[bn + tx * 4 + 3], 0.0f);
        size_t o = (size_t)row * N + bn + tx * 4;
        store_bf16pair4(Chi + o, Clo + o, v);
    }
}

// ---------------------------------------------------------------------------
// LayerNorm: warp per token, outputs bf16 hi/lo pair
// ---------------------------------------------------------------------------
__global__ __launch_bounds__(256) void ln_kernel(
    const float* __restrict__ z, const float* __restrict__ gamma,
    const float* __restrict__ beta, bf16* __restrict__ ohi, bf16* __restrict__ olo)
{
    int warp = threadIdx.x >> 5;
    int lane = threadIdx.x & 31;
    int t = blockIdx.x * 8 + warp;
    const float* zp = z + (size_t)t * DMODEL;

    float4 a = *(const float4*)(zp + lane * 4);
    float4 b = *(const float4*)(zp + 128 + lane * 4);
    float s  = a.x + a.y + a.z + a.w + b.x + b.y + b.z + b.w;
    float sq = a.x*a.x + a.y*a.y + a.z*a.z + a.w*a.w
             + b.x*b.x + b.y*b.y + b.z*b.z + b.w*b.w;
    #pragma unroll
    for (int o = 16; o > 0; o >>= 1) {
        s  += __shfl_xor_sync(0xffffffffu, s,  o);
        sq += __shfl_xor_sync(0xffffffffu, sq, o);
    }
    float mu = s * (1.0f / DMODEL);
    float var = sq * (1.0f / DMODEL) - mu * mu;
    float rs = rsqrtf(var + 1e-5f);

    float4 g0 = *(const float4*)(gamma + lane * 4);
    float4 g1 = *(const float4*)(gamma + 128 + lane * 4);
    float4 be0 = *(const float4*)(beta + lane * 4);
    float4 be1 = *(const float4*)(beta + 128 + lane * 4);
    float4 o0, o1;
    o0.x = (a.x - mu) * rs * g0.x + be0.x;
    o0.y = (a.y - mu) * rs * g0.y + be0.y;
    o0.z = (a.z - mu) * rs * g0.z + be0.z;
    o0.w = (a.w - mu) * rs * g0.w + be0.w;
    o1.x = (b.x - mu) * rs * g1.x + be1.x;
    o1.y = (b.y - mu) * rs * g1.y + be1.y;
    o1.z = (b.z - mu) * rs * g1.z + be1.z;
    o1.w = (b.w - mu) * rs * g1.w + be1.w;
    size_t base = (size_t)t * DMODEL;
    store_bf16pair4(ohi + base + lane * 4,       olo + base + lane * 4,       o0);
    store_bf16pair4(ohi + base + 128 + lane * 4, olo + base + 128 + lane * 4, o1);
}

// ---------------------------------------------------------------------------
// Fused masked attention (TNP-D), outputs bf16 hi/lo pair
// ---------------------------------------------------------------------------
__global__ __launch_bounds__(256) void attn_kernel(
    const float* __restrict__ qkv, bf16* __restrict__ ohi, bf16* __restrict__ olo)
{
    int b = blockIdx.z, h = blockIdx.y;
    int qrow = blockIdx.x * 256 + threadIdx.x;
    int token = b * N_PER_B + qrow;
    const float scale = 0.17677669529663689f;  // 1/sqrt(32)

    float q[DHEAD];
    const float* qp = qkv + (size_t)token * 768 + h * DHEAD;
    #pragma unroll
    for (int d = 0; d < DHEAD; d++) q[d] = qp[d] * scale;

    float mval = -1e30f, l = 0.0f;
    float acc[DHEAD];
    #pragma unroll
    for (int d = 0; d < DHEAD; d++) acc[d] = 0.0f;

    __shared__ float sK[128 * DHEAD];
    __shared__ float sV[128 * DHEAD];

    for (int c = 0; c < 4; c++) {
        __syncthreads();
        for (int i = threadIdx.x; i < 128 * DHEAD; i += 256) {
            int kk = i >> 5, d = i & 31;
            size_t kt = (size_t)(b * N_PER_B + c * 128 + kk) * 768;
            sK[i] = qkv[kt + 256 + h * DHEAD + d];
            sV[i] = qkv[kt + 512 + h * DHEAD + d];
        }
        __syncthreads();
        for (int j = 0; j < 128; j++) {
            const float* kp = sK + j * DHEAD;
            const float* vp = sV + j * DHEAD;
            float s = 0.0f;
            #pragma unroll
            for (int d = 0; d < DHEAD; d++) s += q[d] * kp[d];
            float nm = fmaxf(mval, s);
            float corr = __expf(mval - nm);
            float p = __expf(s - nm);
            l = l * corr + p;
            #pragma unroll
            for (int d = 0; d < DHEAD; d++) acc[d] = acc[d] * corr + p * vp[d];
            mval = nm;
        }
    }

    if (qrow >= NCTX) {
        const float* kp = qkv + (size_t)token * 768 + 256 + h * DHEAD;
        const float* vp = kp + 256;
        float s = 0.0f;
        #pragma unroll
        for (int d = 0; d < DHEAD; d++) s += q[d] * kp[d];
        float nm = fmaxf(mval, s);
        float corr = __expf(mval - nm);
        float p = __expf(s - nm);
        l = l * corr + p;
        #pragma unroll
        for (int d = 0; d < DHEAD; d++) acc[d] = acc[d] * corr + p * vp[d];
        mval = nm;
    }

    float inv = 1.0f / l;
    size_t base = (size_t)token * DMODEL + h * DHEAD;
    #pragma unroll
    for (int d = 0; d < DHEAD; d += 4) {
        float4 v;
        v.x = acc[d + 0] * inv; v.y = acc[d + 1] * inv;
        v.z = acc[d + 2] * inv; v.w = acc[d + 3] * inv;
        store_bf16pair4(ohi + base + d, olo + base + d, v);
    }
}

// ---------------------------------------------------------------------------
// Final copy z -> d_out
// ---------------------------------------------------------------------------
__global__ void copy_kernel(const float* __restrict__ src, float* __restrict__ dst) {
    int i = blockIdx.x * blockDim.x + threadIdx.x;
    ((float4*)dst)[i] = ((const float4*)src)[i];
}

// ---------------------------------------------------------------------------
// Launch
// ---------------------------------------------------------------------------
#define SMEM_BM128 81920   // (2*128+256)*80*2
#define SMEM_BM64  61440   // (2*64+256)*80*2

extern "C" void kernel_launch(void* const* d_in, const int* in_sizes, int n_in,
                              void* d_out, int out_size) {
    const float* xc     = (const float*)d_in[0];
    const float* yc     = (const float*)d_in[1];
    const float* xt     = (const float*)d_in[2];
    const float* enc_W1 = (const float*)d_in[3];
    const float* enc_b1 = (const float*)d_in[4];
    const float* enc_W2 = (const float*)d_in[5];
    const float* enc_b2 = (const float*)d_in[6];
    const float* Wqkv   = (const float*)d_in[7];
    const float* bqkv   = (const float*)d_in[8];
    const float* Wo     = (const float*)d_in[9];
    const float* bo     = (const float*)d_in[10];
    const float* ln1_g  = (const float*)d_in[11];
    const float* ln1_b  = (const float*)d_in[12];
    const float* ln2_g  = (const float*)d_in[13];
    const float* ln2_b  = (const float*)d_in[14];
    const float* Wff1   = (const float*)d_in[15];
    const float* bff1   = (const float*)d_in[16];
    const float* Wff2   = (const float*)d_in[17];
    const float* bff2   = (const float*)d_in[18];

    float *zin, *qkvb, *zb;
    bf16 *ahi, *alo, *fhi, *flo, *wThi, *wTlo;
    cudaGetSymbolAddress((void**)&zin,  g_zin);
    cudaGetSymbolAddress((void**)&qkvb, g_qkv);
    cudaGetSymbolAddress((void**)&zb,   g_z);
    cudaGetSymbolAddress((void**)&ahi,  g_ahi);
    cudaGetSymbolAddress((void**)&alo,  g_alo);
    cudaGetSymbolAddress((void**)&fhi,  g_fhi);
    cudaGetSymbolAddress((void**)&flo,  g_flo);
    cudaGetSymbolAddress((void**)&wThi, g_wThi);
    cudaGetSymbolAddress((void**)&wTlo, g_wTlo);

    cudaFuncSetAttribute(gemm_mma<128, 0, 0, 0>, cudaFuncAttributeMaxDynamicSharedMemorySize, SMEM_BM128);
    cudaFuncSetAttribute(gemm_mma<128, 1, 0, 1>, cudaFuncAttributeMaxDynamicSharedMemorySize, SMEM_BM128);
    cudaFuncSetAttribute(gemm_mma<64, 0, 0, 0>,  cudaFuncAttributeMaxDynamicSharedMemorySize, SMEM_BM64);
    cudaFuncSetAttribute(gemm_mma<64, 0, 1, 0>,  cudaFuncAttributeMaxDynamicSharedMemorySize, SMEM_BM64);

    dim3 tb(32, 8);

    // Weight transposes + bf16 split
    transpose_split<<<dim3(256 / 32, 256 / 32), tb>>>(enc_W2, wThi, wTlo, 256, 256);
    for (int l = 0; l < LAYERS; l++) {
        size_t base = 65536 + (size_t)l * 786432;
        transpose_split<<<dim3(768 / 32, 256 / 32), tb>>>(
            Wqkv + (size_t)l * 256 * 768, wThi + base, wTlo + base, 256, 768);
        transpose_split<<<dim3(256 / 32, 256 / 32), tb>>>(
            Wo + (size_t)l * 256 * 256, wThi + base + 196608, wTlo + base + 196608, 256, 256);
        transpose_split<<<dim3(1024 / 32, 256 / 32), tb>>>(
            Wff1 + (size_t)l * 256 * 1024, wThi + base + 262144, wTlo + base + 262144, 256, 1024);
        transpose_split<<<dim3(256 / 32, 1024 / 32), tb>>>(
            Wff2 + (size_t)l * 1024 * 256, wThi + base + 524288, wTlo + base + 524288, 1024, 256);
    }

    // Encoder
    build_zin_kernel<<<32, 256>>>(xc, yc, xt, zin);
    enc1_kernel<<<dim3(DMODEL / 64, T_TOTAL / 128), 256>>>(zin, enc_W1, enc_b1, ahi, alo);
    gemm_mma<64, 0, 0, 0><<<dim3(2, 128), 256, SMEM_BM64>>>(
        ahi, alo, wThi, wTlo, enc_b2, zb, nullptr, nullptr, 256, 256);

    // Transformer layers
    for (int l = 0; l < LAYERS; l++) {
        size_t base = 65536 + (size_t)l * 786432;
        ln_kernel<<<T_TOTAL / 8, 256>>>(zb, ln1_g + l * DMODEL, ln1_b + l * DMODEL, ahi, alo);
        gemm_mma<128, 0, 0, 0><<<dim3(6, 64), 256, SMEM_BM128>>>(
            ahi, alo, wThi + base, wTlo + base, bqkv + l * 768,
            qkvb, nullptr, nullptr, 768, 256);
        attn_kernel<<<dim3(4, HEADS, 8), 256>>>(qkvb, ahi, alo);
        gemm_mma<64, 0, 1, 0><<<dim3(2, 128), 256, SMEM_BM64>>>(
            ahi, alo, wThi + base + 196608, wTlo + base + 196608, bo + l * DMODEL,
            zb, nullptr, nullptr, 256, 256);
        ln_kernel<<<T_TOTAL / 8, 256>>>(zb, ln2_g + l * DMODEL, ln2_b + l * DMODEL, ahi, alo);
        gemm_mma<128, 1, 0, 1><<<dim3(8, 64), 256, SMEM_BM128>>>(
            ahi, alo, wThi + base + 262144, wTlo + base + 262144, bff1 + l * FFDIM,
            nullptr, fhi, flo, 1024, 256);
        gemm_mma<64, 0, 1, 0><<<dim3(2, 128), 256, SMEM_BM64>>>(
            fhi, flo, wThi + base + 524288, wTlo + base + 524288, bff2 + l * DMODEL,
            zb, nullptr, nullptr, 256, 1024);
    }

    copy_kernel<<<(T_TOTAL * DMODEL / 4) / 256, 256>>>(zb, (float*)d_out);
}